// round 11
// baseline (speedup 1.0000x reference)
#include <cuda_runtime.h>

// ---------------------------------------------------------------------------
// Problem constants
// ---------------------------------------------------------------------------
#define NB    64                     // graphs
#define NPG   2048                   // nodes per graph
#define NTOT  (NB * NPG)             // 131072 nodes
#define EPG   32768
#define ETOT  (NB * EPG)             // 2097152 edges
#define DD    32                     // feature dim
#define KKEEP 1024                   // kept per graph (ratio 0.5)
#define MAXDEG 80                    // P(Poisson(16) >= 80) ~ 1e-30

// Output layout (flattened reference tuple, all as float32)
#define X5_OFF     0
#define EI_OFF     (NB * KKEEP * DD)        // 2097152
#define EA_OFF     (EI_OFF + 2 * ETOT)      // 6291456
#define NBATCH_OFF (EA_OFF + ETOT)          // 8388608
#define PERM_OFF   (NBATCH_OFF + NB * KKEEP)
#define SC_OFF     (PERM_OFF + NB * KKEEP)

// ---------------------------------------------------------------------------
// Device scratch (static — no allocation allowed)
// ---------------------------------------------------------------------------
__device__ float g_agg[NTOT * DD];    // 16 MB : segment_sum(x[src], dst)
__device__ float g_x3[NTOT * DD];     // 16 MB : third conv output
__device__ float g_score[NTOT];
__device__ int   g_newidx[NTOT];      // relabel map (-1 = dropped)
__device__ int   g_deg[NTOT];
__device__ int   g_off[NTOT];
__device__ int   g_cur[NTOT];
__device__ int   g_elist[ETOT];       // edge ids grouped by dst (unsorted within node)

// ---------------------------------------------------------------------------
// Kernel 1: init per-launch state (replay determinism)
// ---------------------------------------------------------------------------
__global__ void k_init() {
    int i = blockIdx.x * blockDim.x + threadIdx.x;
    if (i < NTOT) { g_deg[i] = 0; g_cur[i] = 0; g_newidx[i] = -1; }
}

// ---------------------------------------------------------------------------
// Kernel 2: degree count (int atomics — order-independent, deterministic)
// ---------------------------------------------------------------------------
__global__ void k_count(const int* __restrict__ ei) {
    int e = blockIdx.x * blockDim.x + threadIdx.x;
    if (e < ETOT) atomicAdd(&g_deg[ei[ETOT + e]], 1);
}

// ---------------------------------------------------------------------------
// Kernel 3: exclusive scan of degrees (single block, 1024 threads x 128)
// ---------------------------------------------------------------------------
__global__ void __launch_bounds__(1024) k_scan() {
    __shared__ int ssum[1024];
    int t = threadIdx.x;
    int base = t * (NTOT / 1024);      // 128 per thread
    int s = 0;
    for (int i = 0; i < NTOT / 1024; i++) s += g_deg[base + i];
    ssum[t] = s;
    __syncthreads();
    for (int off = 1; off < 1024; off <<= 1) {
        int v = (t >= off) ? ssum[t - off] : 0;
        __syncthreads();
        ssum[t] += v;
        __syncthreads();
    }
    int run = ssum[t] - s;             // exclusive prefix for this thread's chunk
    for (int i = 0; i < NTOT / 1024; i++) {
        g_off[base + i] = run;
        run += g_deg[base + i];
    }
}

// ---------------------------------------------------------------------------
// Kernel 4: fill CSR edge lists (slot order arbitrary; sorted later)
// ---------------------------------------------------------------------------
__global__ void k_fill(const int* __restrict__ ei) {
    int e = blockIdx.x * blockDim.x + threadIdx.x;
    if (e >= ETOT) return;
    int d = ei[ETOT + e];
    int pos = g_off[d] + atomicAdd(&g_cur[d], 1);
    g_elist[pos] = e;
}

// ---------------------------------------------------------------------------
// Kernel 5: per-node gather-sum in ASCENDING EDGE ORDER.
// One thread per node: sort its edge-id list ascending, then accumulate
// agg[d] += x[src[e]][d] sequentially — bitwise-matches XLA CPU scatter-add,
// which applies updates in index order.
// ---------------------------------------------------------------------------
__global__ void k_gather(const float* __restrict__ x, const int* __restrict__ ei) {
    int n = blockIdx.x * blockDim.x + threadIdx.x;
    if (n >= NTOT) return;
    int deg = g_deg[n];
    int off = g_off[n];
    if (deg > MAXDEG) deg = MAXDEG;    // statistically unreachable

    int list[MAXDEG];
    for (int i = 0; i < deg; i++) list[i] = g_elist[off + i];
    // insertion sort ascending (avg deg ~16)
    for (int i = 1; i < deg; i++) {
        int key = list[i];
        int j = i - 1;
        while (j >= 0 && list[j] > key) { list[j + 1] = list[j]; j--; }
        list[j + 1] = key;
    }

    float4 a[8];
#pragma unroll
    for (int q = 0; q < 8; q++) a[q] = make_float4(0.f, 0.f, 0.f, 0.f);

    for (int i = 0; i < deg; i++) {
        int s = ei[list[i]];           // src of edge
        const float4* r = reinterpret_cast<const float4*>(x + (size_t)s * DD);
#pragma unroll
        for (int q = 0; q < 8; q++) {
            float4 v = r[q];
            a[q].x += v.x; a[q].y += v.y; a[q].z += v.z; a[q].w += v.w;
        }
    }
    float4* dst = reinterpret_cast<float4*>(g_agg + (size_t)n * DD);
#pragma unroll
    for (int q = 0; q < 8; q++) dst[q] = a[q];
}

// ---------------------------------------------------------------------------
// Kernel 6: per-node transforms, fp-order matched to reference:
//   out = (x@W_root + agg@W_rel) + b : two separate k-ascending FMA chains,
//   then add, then bias. score = seq-sum(x2*y2) / sqrt32 (IEEE div).
// One warp per node; lane = output dim.
// ---------------------------------------------------------------------------
__global__ void k_trans(const float* __restrict__ x,
                        const float* __restrict__ Wr1, const float* __restrict__ Wl1, const float* __restrict__ b1,
                        const float* __restrict__ Wr2, const float* __restrict__ Wl2, const float* __restrict__ b2,
                        const float* __restrict__ Wr3, const float* __restrict__ Wl3, const float* __restrict__ b3) {
    __shared__ float sW[6][DD * DD];
    int tid = threadIdx.x;
    for (int i = tid; i < DD * DD; i += blockDim.x) {
        sW[0][i] = Wr1[i]; sW[1][i] = Wl1[i];
        sW[2][i] = Wr2[i]; sW[3][i] = Wl2[i];
        sW[4][i] = Wr3[i]; sW[5][i] = Wl3[i];
    }
    __syncthreads();

    int warp = tid >> 5, lane = tid & 31;
    int node = blockIdx.x * (blockDim.x >> 5) + warp;
    if (node >= NTOT) return;

    float xv = x[(size_t)node * DD + lane];
    float av = g_agg[(size_t)node * DD + lane];
    float r1 = 0.f, l1 = 0.f, r2 = 0.f, l2 = 0.f, r3 = 0.f, l3 = 0.f;

#pragma unroll
    for (int k = 0; k < DD; k++) {
        float xk = __shfl_sync(0xffffffffu, xv, k);
        float ak = __shfl_sync(0xffffffffu, av, k);
        r1 = fmaf(xk, sW[0][k * DD + lane], r1);
        l1 = fmaf(ak, sW[1][k * DD + lane], l1);
        r2 = fmaf(xk, sW[2][k * DD + lane], r2);
        l2 = fmaf(ak, sW[3][k * DD + lane], l2);
        r3 = fmaf(xk, sW[4][k * DD + lane], r3);
        l3 = fmaf(ak, sW[5][k * DD + lane], l3);
    }
    float o1 = __fadd_rn(__fadd_rn(r1, l1), b1[lane]);
    float o2 = __fadd_rn(__fadd_rn(r2, l2), b2[lane]);
    float o3 = __fadd_rn(__fadd_rn(r3, l3), b3[lane]);

    g_x3[(size_t)node * DD + lane] = o3;

    // score = sum_d (o1*o2) / sqrt(32), summed sequentially ascending d
    float p = __fmul_rn(o1, o2);
    float s = 0.f;
#pragma unroll
    for (int k = 0; k < DD; k++)
        s = __fadd_rn(s, __shfl_sync(0xffffffffu, p, k));
    const float SQRT32 = 5.65685415267944336f;   // fp32(sqrt(32))
    if (lane == 0)
        g_score[node] = __fdiv_rn(s, SQRT32);
}

// ---------------------------------------------------------------------------
// Kernel 7: per-graph top-K via bitonic sort of 2048 packed keys.
// key = (~ordered(score) << 32) | index -> ascending sort == score desc,
// index-asc tiebreak (matches lax.top_k).
// ---------------------------------------------------------------------------
__global__ void __launch_bounds__(1024) k_topk(const float* __restrict__ x,
                                               float* __restrict__ out) {
    __shared__ unsigned long long key[NPG];
    int b = blockIdx.x, tid = threadIdx.x;

    for (int j = tid; j < NPG; j += 1024) {
        float s = g_score[b * NPG + j];
        unsigned u = __float_as_uint(s);
        u = (u & 0x80000000u) ? ~u : (u | 0x80000000u);
        key[j] = ((unsigned long long)(~u) << 32) | (unsigned)j;
    }
    __syncthreads();

    for (int k = 2; k <= NPG; k <<= 1) {
        for (int j = k >> 1; j > 0; j >>= 1) {
            for (int t = tid; t < NPG; t += 1024) {
                int l = t ^ j;
                if (l > t) {
                    bool asc = ((t & k) == 0);
                    unsigned long long a = key[t], c = key[l];
                    if ((a > c) == asc) { key[t] = c; key[l] = a; }
                }
            }
            __syncthreads();
        }
    }

    if (tid < KKEEP) {
        int li   = (int)(key[tid] & 0xffffffffu);
        int node = b * NPG + li;
        int row  = b * KKEEP + tid;
        g_newidx[node] = row;
        float s = g_score[node];
        out[PERM_OFF + row]   = (float)node;
        out[NBATCH_OFF + row] = (float)b;
        out[SC_OFF + row]     = s;
        const float* xr  = x    + (size_t)node * DD;
        const float* x3r = g_x3 + (size_t)node * DD;
#pragma unroll
        for (int d = 0; d < DD; d++)   // x + (s*x3): mul then add, no FMA
            out[X5_OFF + (size_t)row * DD + d] =
                __fadd_rn(xr[d], __fmul_rn(s, x3r[d]));
    }
}

// ---------------------------------------------------------------------------
// Kernel 8: edge relabel / filter
// ---------------------------------------------------------------------------
__global__ void k_edge(const int* __restrict__ ei, const float* __restrict__ attr,
                       float* __restrict__ out) {
    int e = blockIdx.x * blockDim.x + threadIdx.x;
    if (e >= ETOT) return;
    int ns = g_newidx[ei[e]];
    int nd = g_newidx[ei[ETOT + e]];
    bool v = (ns >= 0) && (nd >= 0);
    out[EI_OFF + e]        = v ? (float)ns : -1.0f;
    out[EI_OFF + ETOT + e] = v ? (float)nd : -1.0f;
    out[EA_OFF + e]        = v ? attr[e] : 0.0f;
}

// ---------------------------------------------------------------------------
// Launch
// ---------------------------------------------------------------------------
extern "C" void kernel_launch(void* const* d_in, const int* in_sizes, int n_in,
                              void* d_out, int out_size) {
    const float* x    = (const float*)d_in[0];
    const int*   ei   = (const int*)d_in[1];
    const float* attr = (const float*)d_in[2];
    // d_in[3] = batch (unused; new_batch derived from graph id)
    const float* Wr1 = (const float*)d_in[4];
    const float* Wl1 = (const float*)d_in[5];
    const float* b1  = (const float*)d_in[6];
    const float* Wr2 = (const float*)d_in[7];
    const float* Wl2 = (const float*)d_in[8];
    const float* b2  = (const float*)d_in[9];
    const float* Wr3 = (const float*)d_in[10];
    const float* Wl3 = (const float*)d_in[11];
    const float* b3  = (const float*)d_in[12];
    float* out = (float*)d_out;

    k_init  <<<(NTOT + 255) / 256, 256>>>();
    k_count <<<(ETOT + 255) / 256, 256>>>(ei);
    k_scan  <<<1, 1024>>>();
    k_fill  <<<(ETOT + 255) / 256, 256>>>(ei);
    k_gather<<<(NTOT + 255) / 256, 256>>>(x, ei);
    k_trans <<<NTOT / 8, 256>>>(x, Wr1, Wl1, b1, Wr2, Wl2, b2, Wr3, Wl3, b3);
    k_topk  <<<NB, 1024>>>(x, out);
    k_edge  <<<(ETOT + 255) / 256, 256>>>(ei, attr, out);
}

// round 12
// speedup vs baseline: 2.5211x; 2.5211x over previous
#include <cuda_runtime.h>

// ---------------------------------------------------------------------------
// Problem constants
// ---------------------------------------------------------------------------
#define NB    64                     // graphs
#define NPG   2048                   // nodes per graph
#define NTOT  (NB * NPG)             // 131072 nodes
#define EPG   32768
#define ETOT  (NB * EPG)             // 2097152 edges
#define DD    32                     // feature dim
#define KKEEP 1024                   // kept per graph (ratio 0.5)
#define NKEPT (NB * KKEEP)           // 65536
#define MAXDEG 64                    // slow-path cap; P(Poisson(16) >= 64) ~ 0

// Output layout (flattened reference tuple, all as float32)
#define X5_OFF     0
#define EI_OFF     (NKEPT * DD)             // 2097152
#define EA_OFF     (EI_OFF + 2 * ETOT)      // 6291456
#define NBATCH_OFF (EA_OFF + ETOT)          // 8388608
#define PERM_OFF   (NBATCH_OFF + NKEPT)
#define SC_OFF     (PERM_OFF + NKEPT)

#define FULLMASK 0xffffffffu

// ---------------------------------------------------------------------------
// Device scratch (static — no allocation allowed)
// ---------------------------------------------------------------------------
__device__ float              g_agg[NTOT * DD];   // 16 MB
__device__ float              g_score[NTOT];
__device__ int                g_newidx[NTOT];     // relabel map (-1 = dropped)
__device__ int                g_kept[NKEPT];      // kept node per output row
__device__ int                g_deg[NTOT];
__device__ int                g_off[NTOT];
__device__ int                g_cur[NTOT];
__device__ int                g_bsum[512];
__device__ int                g_bsumx[512];
__device__ unsigned long long g_elist[ETOT];      // packed (e<<17 | src), grouped by dst

// ---------------------------------------------------------------------------
// Kernel 1: init per-launch state (replay determinism)
// ---------------------------------------------------------------------------
__global__ void k_init() {
    int i = blockIdx.x * blockDim.x + threadIdx.x;
    if (i < NTOT) { g_deg[i] = 0; g_newidx[i] = -1; }
}

// ---------------------------------------------------------------------------
// Kernel 2: degree count (int atomics — order-independent, deterministic)
// ---------------------------------------------------------------------------
__global__ void k_count(const int* __restrict__ ei) {
    int e = blockIdx.x * blockDim.x + threadIdx.x;
    if (e < ETOT) atomicAdd(&g_deg[ei[ETOT + e]], 1);
}

// ---------------------------------------------------------------------------
// Kernels 3a/3b/3c: hierarchical exclusive scan of degrees (all coalesced)
// ---------------------------------------------------------------------------
__global__ void k_scanA() {                       // 512 blocks x 256: block sums
    __shared__ int sh[256];
    int t = threadIdx.x;
    sh[t] = g_deg[blockIdx.x * 256 + t];
    __syncthreads();
    for (int off = 128; off > 0; off >>= 1) {
        if (t < off) sh[t] += sh[t + off];
        __syncthreads();
    }
    if (t == 0) g_bsum[blockIdx.x] = sh[0];
}

__global__ void __launch_bounds__(512) k_scanB() { // 1 block x 512: scan of block sums
    __shared__ int sh[512];
    int t = threadIdx.x;
    int v = g_bsum[t];
    sh[t] = v;
    __syncthreads();
    for (int off = 1; off < 512; off <<= 1) {
        int u = (t >= off) ? sh[t - off] : 0;
        __syncthreads();
        sh[t] += u;
        __syncthreads();
    }
    g_bsumx[t] = sh[t] - v;                        // exclusive
}

__global__ void k_scanC() {                        // 512 blocks x 256: final offsets
    __shared__ int sh[256];
    int t = threadIdx.x;
    int i = blockIdx.x * 256 + t;
    int v = g_deg[i];
    sh[t] = v;
    __syncthreads();
    for (int off = 1; off < 256; off <<= 1) {
        int u = (t >= off) ? sh[t - off] : 0;
        __syncthreads();
        sh[t] += u;
        __syncthreads();
    }
    g_off[i] = (sh[t] - v) + g_bsumx[blockIdx.x];
    g_cur[i] = 0;
}

// ---------------------------------------------------------------------------
// Kernel 4: fill CSR lists with packed (edge_id << 17) | src.
// Slot order arbitrary (atomic); sorted by the gather via the packed key.
// ---------------------------------------------------------------------------
__global__ void k_fill(const int* __restrict__ ei) {
    int e = blockIdx.x * blockDim.x + threadIdx.x;
    if (e >= ETOT) return;
    int s = ei[e];
    int d = ei[ETOT + e];
    int pos = g_off[d] + atomicAdd(&g_cur[d], 1);
    g_elist[pos] = ((unsigned long long)e << 17) | (unsigned)s;
}

// ---------------------------------------------------------------------------
// Kernel 5: gather-sum, warp per node, ASCENDING EDGE ORDER (bitwise match
// to XLA CPU scatter-add). Fast path deg<=32: register bitonic sort via
// shuffles (no local memory). Rare deg>32: lane-0 insertion sort in shared.
// lane = feature dim -> every x-row read is one coalesced 128B load.
// ---------------------------------------------------------------------------
__global__ void k_gather(const float* __restrict__ x) {
    __shared__ unsigned long long sl[8][MAXDEG];
    int tid  = threadIdx.x;
    int warp = tid >> 5, lane = tid & 31;
    int n = blockIdx.x * 8 + warp;
    if (n >= NTOT) return;

    int deg = g_deg[n];
    int off = g_off[n];
    float acc = 0.0f;

    if (deg <= 32) {
        unsigned long long v = (lane < deg) ? g_elist[off + lane]
                                            : 0xffffffffffffffffULL;
        // bitonic sort 32 across lanes, ascending
#pragma unroll
        for (int k = 2; k <= 32; k <<= 1) {
#pragma unroll
            for (int j = k >> 1; j > 0; j >>= 1) {
                unsigned long long o = __shfl_xor_sync(FULLMASK, v, j);
                bool up    = ((lane & k) == 0);
                bool lower = ((lane & j) == 0);
                if (up == lower) v = (v < o) ? v : o;
                else             v = (v > o) ? v : o;
            }
        }
        unsigned mysrc = (unsigned)(v & 0x1ffffu);
        for (int i = 0; i < deg; i++) {
            unsigned s = __shfl_sync(FULLMASK, mysrc, i);
            acc = __fadd_rn(acc, x[(size_t)s * DD + lane]);
        }
    } else {
        int degc = (deg > MAXDEG) ? MAXDEG : deg;
        if (lane == 0) {
            for (int i = 0; i < degc; i++) sl[warp][i] = g_elist[off + i];
            for (int i = 1; i < degc; i++) {           // insertion sort asc
                unsigned long long key = sl[warp][i];
                int j = i - 1;
                while (j >= 0 && sl[warp][j] > key) { sl[warp][j + 1] = sl[warp][j]; j--; }
                sl[warp][j + 1] = key;
            }
        }
        __syncwarp();
        for (int i = 0; i < degc; i++) {
            unsigned s = (unsigned)(sl[warp][i] & 0x1ffffu);
            acc = __fadd_rn(acc, x[(size_t)s * DD + lane]);
        }
    }
    g_agg[(size_t)n * DD + lane] = acc;
}

// ---------------------------------------------------------------------------
// Kernel 6: layers 1+2 and score only (layer 3 deferred to kept nodes).
// 2 nodes per warp (lane = output dim), amortizing weight LDS across nodes.
// Per-node fp chains identical to the passing version:
//   r,l : k-ascending FMA chains; o = (r+l)+b; score = seq-sum(o1*o2)/sqrt32.
// ---------------------------------------------------------------------------
__global__ void k_trans(const float* __restrict__ x,
                        const float* __restrict__ Wr1, const float* __restrict__ Wl1, const float* __restrict__ b1,
                        const float* __restrict__ Wr2, const float* __restrict__ Wl2, const float* __restrict__ b2) {
    __shared__ float sW[4][DD * DD];
    int tid = threadIdx.x;
    for (int i = tid; i < DD * DD; i += blockDim.x) {
        sW[0][i] = Wr1[i]; sW[1][i] = Wl1[i];
        sW[2][i] = Wr2[i]; sW[3][i] = Wl2[i];
    }
    __syncthreads();

    int warp = tid >> 5, lane = tid & 31;
    int nA = (blockIdx.x * 8 + warp) * 2;     // 8 warps x 2 nodes per block
    int nB = nA + 1;
    if (nA >= NTOT) return;

    float xvA = x[(size_t)nA * DD + lane];
    float avA = g_agg[(size_t)nA * DD + lane];
    float xvB = x[(size_t)nB * DD + lane];
    float avB = g_agg[(size_t)nB * DD + lane];

    float r1A = 0.f, l1A = 0.f, r2A = 0.f, l2A = 0.f;
    float r1B = 0.f, l1B = 0.f, r2B = 0.f, l2B = 0.f;

#pragma unroll
    for (int k = 0; k < DD; k++) {
        float xkA = __shfl_sync(FULLMASK, xvA, k);
        float akA = __shfl_sync(FULLMASK, avA, k);
        float xkB = __shfl_sync(FULLMASK, xvB, k);
        float akB = __shfl_sync(FULLMASK, avB, k);
        float w0 = sW[0][k * DD + lane];
        float w1 = sW[1][k * DD + lane];
        float w2 = sW[2][k * DD + lane];
        float w3 = sW[3][k * DD + lane];
        r1A = fmaf(xkA, w0, r1A);  l1A = fmaf(akA, w1, l1A);
        r2A = fmaf(xkA, w2, r2A);  l2A = fmaf(akA, w3, l2A);
        r1B = fmaf(xkB, w0, r1B);  l1B = fmaf(akB, w1, l1B);
        r2B = fmaf(xkB, w2, r2B);  l2B = fmaf(akB, w3, l2B);
    }
    float bb1 = b1[lane], bb2 = b2[lane];
    float o1A = __fadd_rn(__fadd_rn(r1A, l1A), bb1);
    float o2A = __fadd_rn(__fadd_rn(r2A, l2A), bb2);
    float o1B = __fadd_rn(__fadd_rn(r1B, l1B), bb1);
    float o2B = __fadd_rn(__fadd_rn(r2B, l2B), bb2);

    float pA = __fmul_rn(o1A, o2A);
    float pB = __fmul_rn(o1B, o2B);
    float sA = 0.f, sB = 0.f;
#pragma unroll
    for (int k = 0; k < DD; k++) {            // sequential ascending-d sum
        sA = __fadd_rn(sA, __shfl_sync(FULLMASK, pA, k));
        sB = __fadd_rn(sB, __shfl_sync(FULLMASK, pB, k));
    }
    const float SQRT32 = 5.65685415267944336f;
    if (lane == 0) {
        g_score[nA] = __fdiv_rn(sA, SQRT32);
        g_score[nB] = __fdiv_rn(sB, SQRT32);
    }
}

// ---------------------------------------------------------------------------
// Kernel 7: per-graph top-K via bitonic sort of 2048 packed keys.
// key = (~ordered(score) << 32) | index -> ascending == score desc,
// index-asc tiebreak (matches lax.top_k). Emits perm/batch/score + kept list.
// ---------------------------------------------------------------------------
__global__ void __launch_bounds__(1024) k_topk(float* __restrict__ out) {
    __shared__ unsigned long long key[NPG];
    int b = blockIdx.x, tid = threadIdx.x;

    for (int j = tid; j < NPG; j += 1024) {
        float s = g_score[b * NPG + j];
        unsigned u = __float_as_uint(s);
        u = (u & 0x80000000u) ? ~u : (u | 0x80000000u);
        key[j] = ((unsigned long long)(~u) << 32) | (unsigned)j;
    }
    __syncthreads();

    for (int k = 2; k <= NPG; k <<= 1) {
        for (int j = k >> 1; j > 0; j >>= 1) {
            for (int t = tid; t < NPG; t += 1024) {
                int l = t ^ j;
                if (l > t) {
                    bool asc = ((t & k) == 0);
                    unsigned long long a = key[t], c = key[l];
                    if ((a > c) == asc) { key[t] = c; key[l] = a; }
                }
            }
            __syncthreads();
        }
    }

    if (tid < KKEEP) {
        int li   = (int)(key[tid] & 0xffffffffu);
        int node = b * NPG + li;
        int row  = b * KKEEP + tid;
        g_newidx[node] = row;
        g_kept[row]    = node;
        out[PERM_OFF + row]   = (float)node;
        out[NBATCH_OFF + row] = (float)b;
        out[SC_OFF + row]     = g_score[node];
    }
}

// ---------------------------------------------------------------------------
// Kernel 8: layer 3 + skip connection for KEPT nodes only.
// Same FMA chain as the full layer -> identical bits to previous version.
// ---------------------------------------------------------------------------
__global__ void k_x5(const float* __restrict__ x,
                     const float* __restrict__ Wr3, const float* __restrict__ Wl3,
                     const float* __restrict__ b3, float* __restrict__ out) {
    __shared__ float sW[2][DD * DD];
    int tid = threadIdx.x;
    for (int i = tid; i < DD * DD; i += blockDim.x) {
        sW[0][i] = Wr3[i]; sW[1][i] = Wl3[i];
    }
    __syncthreads();

    int warp = tid >> 5, lane = tid & 31;
    int row = blockIdx.x * 8 + warp;
    if (row >= NKEPT) return;
    int node = g_kept[row];

    float xv = x[(size_t)node * DD + lane];
    float av = g_agg[(size_t)node * DD + lane];
    float r3 = 0.f, l3 = 0.f;
#pragma unroll
    for (int k = 0; k < DD; k++) {
        float xk = __shfl_sync(FULLMASK, xv, k);
        float ak = __shfl_sync(FULLMASK, av, k);
        r3 = fmaf(xk, sW[0][k * DD + lane], r3);
        l3 = fmaf(ak, sW[1][k * DD + lane], l3);
    }
    float o3 = __fadd_rn(__fadd_rn(r3, l3), b3[lane]);
    float s  = g_score[node];
    out[X5_OFF + (size_t)row * DD + lane] = __fadd_rn(xv, __fmul_rn(s, o3));
}

// ---------------------------------------------------------------------------
// Kernel 9: edge relabel / filter
// ---------------------------------------------------------------------------
__global__ void k_edge(const int* __restrict__ ei, const float* __restrict__ attr,
                       float* __restrict__ out) {
    int e = blockIdx.x * blockDim.x + threadIdx.x;
    if (e >= ETOT) return;
    int ns = g_newidx[ei[e]];
    int nd = g_newidx[ei[ETOT + e]];
    bool v = (ns >= 0) && (nd >= 0);
    out[EI_OFF + e]        = v ? (float)ns : -1.0f;
    out[EI_OFF + ETOT + e] = v ? (float)nd : -1.0f;
    out[EA_OFF + e]        = v ? attr[e] : 0.0f;
}

// ---------------------------------------------------------------------------
// Launch
// ---------------------------------------------------------------------------
extern "C" void kernel_launch(void* const* d_in, const int* in_sizes, int n_in,
                              void* d_out, int out_size) {
    const float* x    = (const float*)d_in[0];
    const int*   ei   = (const int*)d_in[1];
    const float* attr = (const float*)d_in[2];
    // d_in[3] = batch (unused; new_batch derived from graph id)
    const float* Wr1 = (const float*)d_in[4];
    const float* Wl1 = (const float*)d_in[5];
    const float* b1  = (const float*)d_in[6];
    const float* Wr2 = (const float*)d_in[7];
    const float* Wl2 = (const float*)d_in[8];
    const float* b2  = (const float*)d_in[9];
    const float* Wr3 = (const float*)d_in[10];
    const float* Wl3 = (const float*)d_in[11];
    const float* b3  = (const float*)d_in[12];
    float* out = (float*)d_out;

    k_init  <<<(NTOT + 255) / 256, 256>>>();
    k_count <<<(ETOT + 255) / 256, 256>>>(ei);
    k_scanA <<<512, 256>>>();
    k_scanB <<<1, 512>>>();
    k_scanC <<<512, 256>>>();
    k_fill  <<<(ETOT + 255) / 256, 256>>>(ei);
    k_gather<<<(NTOT + 7) / 8, 256>>>(x);
    k_trans <<<NTOT / 16, 256>>>(x, Wr1, Wl1, b1, Wr2, Wl2, b2);
    k_topk  <<<NB, 1024>>>(out);
    k_x5    <<<NKEPT / 8, 256>>>(x, Wr3, Wl3, b3, out);
    k_edge  <<<(ETOT + 255) / 256, 256>>>(ei, attr, out);
}

// round 15
// speedup vs baseline: 2.5592x; 1.0151x over previous
#include <cuda_runtime.h>

// ---------------------------------------------------------------------------
// Problem constants
// ---------------------------------------------------------------------------
#define NB    64                     // graphs
#define NPG   2048                   // nodes per graph (2^11)
#define NTOT  (NB * NPG)             // 131072 nodes
#define EPG   32768                  // edges per graph (2^15)
#define ETOT  (NB * EPG)             // 2097152 edges
#define DD    32                     // feature dim
#define KKEEP 1024                   // kept per graph (ratio 0.5)
#define NKEPT (NB * KKEEP)           // 65536
#define MAXDEG 64                    // slow-path cap; P(Binom>=64) ~ 0

// Output layout (flattened reference tuple, all as float32)
#define X5_OFF     0
#define EI_OFF     (NKEPT * DD)             // 2097152
#define EA_OFF     (EI_OFF + 2 * ETOT)      // 6291456
#define NBATCH_OFF (EA_OFF + ETOT)          // 8388608
#define PERM_OFF   (NBATCH_OFF + NKEPT)
#define SC_OFF     (PERM_OFF + NKEPT)

#define FULLMASK 0xffffffffu

// ---------------------------------------------------------------------------
// Device scratch (static — no allocation allowed)
// ---------------------------------------------------------------------------
__device__ float    g_agg[NTOT * DD];   // 16 MB
__device__ float    g_score[NTOT];
__device__ int      g_newidx[NTOT];     // relabel map (-1 = dropped); fully written by k_topk
__device__ int      g_deg[NTOT];
__device__ int      g_off[NTOT];        // global CSR offset (includes g*EPG base)
__device__ int      g_cur[NTOT];
__device__ unsigned g_elist[ETOT];      // packed (e_local<<11 | src_local), grouped by dst

// ---------------------------------------------------------------------------
// Kernel 1: zero degree counters (replay determinism)
// ---------------------------------------------------------------------------
__global__ void k_init() {
    int i = blockIdx.x * blockDim.x + threadIdx.x;
    if (i < NTOT) g_deg[i] = 0;
}

// ---------------------------------------------------------------------------
// Kernel 2: degree count (int atomics — order-independent, deterministic)
// ---------------------------------------------------------------------------
__global__ void k_count(const int* __restrict__ ei) {
    int e = blockIdx.x * blockDim.x + threadIdx.x;
    if (e < ETOT) atomicAdd(&g_deg[ei[ETOT + e]], 1);
}

// ---------------------------------------------------------------------------
// Kernel 3: per-graph exclusive scan of degrees (one block per graph).
// Graph g's edges occupy [g*EPG, (g+1)*EPG) -> no cross-graph dependency.
// Also resets g_cur.
// ---------------------------------------------------------------------------
__global__ void __launch_bounds__(1024) k_scan() {
    __shared__ int sh[1024];
    int g = blockIdx.x, t = threadIdx.x;
    int base = g * NPG;
    int v0 = g_deg[base + 2 * t];
    int v1 = g_deg[base + 2 * t + 1];
    int s = v0 + v1;
    sh[t] = s;
    __syncthreads();
    for (int off = 1; off < 1024; off <<= 1) {
        int u = (t >= off) ? sh[t - off] : 0;
        __syncthreads();
        sh[t] += u;
        __syncthreads();
    }
    int ex = sh[t] - s;                         // exclusive prefix of pair
    int ebase = g * EPG;
    g_off[base + 2 * t]     = ebase + ex;
    g_off[base + 2 * t + 1] = ebase + ex + v0;
    g_cur[base + 2 * t]     = 0;
    g_cur[base + 2 * t + 1] = 0;
}

// ---------------------------------------------------------------------------
// Kernel 4: fill CSR lists with packed (e_local << 11) | src_local.
// Sorting by this 26-bit key == sorting by global edge id (stability of the
// ascending-edge-order sum preserved). Slot order arbitrary (atomic).
// ---------------------------------------------------------------------------
__global__ void k_fill(const int* __restrict__ ei) {
    int e = blockIdx.x * blockDim.x + threadIdx.x;
    if (e >= ETOT) return;
    int s = ei[e];
    int d = ei[ETOT + e];
    unsigned e_local = (unsigned)(e & (EPG - 1));
    unsigned s_local = (unsigned)(s & (NPG - 1));
    int pos = g_off[d] + atomicAdd(&g_cur[d], 1);
    g_elist[pos] = (e_local << 11) | s_local;
}

// ---------------------------------------------------------------------------
// Kernel 5: gather-sum, warp per node, ASCENDING EDGE ORDER (bitwise match
// to XLA CPU scatter-add). Fast path deg<=32: 32-bit register bitonic sort
// via shuffles. Rare deg>32 (~1 node): lane-0 insertion sort in shared.
// lane = feature dim -> each x-row read is one coalesced 128B load.
// ---------------------------------------------------------------------------
__global__ void k_gather(const float* __restrict__ x) {
    __shared__ unsigned sl[8][MAXDEG];
    int tid  = threadIdx.x;
    int warp = tid >> 5, lane = tid & 31;
    int n = blockIdx.x * 8 + warp;
    if (n >= NTOT) return;

    int deg = g_deg[n];
    int off = g_off[n];
    unsigned sbase = (unsigned)(n >> 11) << 11;   // graph node base
    float acc = 0.0f;

    if (deg <= 32) {
        unsigned v = (lane < deg) ? g_elist[off + lane] : 0xffffffffu;
        // bitonic sort 32 across lanes, ascending
#pragma unroll
        for (int k = 2; k <= 32; k <<= 1) {
#pragma unroll
            for (int j = k >> 1; j > 0; j >>= 1) {
                unsigned o = __shfl_xor_sync(FULLMASK, v, j);
                bool up    = ((lane & k) == 0);
                bool lower = ((lane & j) == 0);
                if (up == lower) v = (v < o) ? v : o;
                else             v = (v > o) ? v : o;
            }
        }
        unsigned mysrc = sbase + (v & 0x7ffu);
        for (int i = 0; i < deg; i++) {
            unsigned s = __shfl_sync(FULLMASK, mysrc, i);
            acc = __fadd_rn(acc, x[(size_t)s * DD + lane]);
        }
    } else {
        int degc = (deg > MAXDEG) ? MAXDEG : deg;
        if (lane == 0) {
            for (int i = 0; i < degc; i++) sl[warp][i] = g_elist[off + i];
            for (int i = 1; i < degc; i++) {          // insertion sort asc
                unsigned key = sl[warp][i];
                int j = i - 1;
                while (j >= 0 && sl[warp][j] > key) { sl[warp][j + 1] = sl[warp][j]; j--; }
                sl[warp][j + 1] = key;
            }
        }
        __syncwarp();
        for (int i = 0; i < degc; i++) {
            unsigned s = sbase + (sl[warp][i] & 0x7ffu);
            acc = __fadd_rn(acc, x[(size_t)s * DD + lane]);
        }
    }
    g_agg[(size_t)n * DD + lane] = acc;
}

// ---------------------------------------------------------------------------
// Kernel 6: layers 1+2 and score. 4 nodes per warp (lane = output dim),
// weight LDS amortized 4x. Per-node fp chains identical to passing version:
//   r,l : k-ascending FMA chains; o = (r+l)+b; score = seq-sum(o1*o2)/sqrt32.
// ---------------------------------------------------------------------------
__global__ void k_trans(const float* __restrict__ x,
                        const float* __restrict__ Wr1, const float* __restrict__ Wl1, const float* __restrict__ b1,
                        const float* __restrict__ Wr2, const float* __restrict__ Wl2, const float* __restrict__ b2) {
    __shared__ float sW[4][DD * DD];
    int tid = threadIdx.x;
    for (int i = tid; i < DD * DD; i += blockDim.x) {
        sW[0][i] = Wr1[i]; sW[1][i] = Wl1[i];
        sW[2][i] = Wr2[i]; sW[3][i] = Wl2[i];
    }
    __syncthreads();

    int warp = tid >> 5, lane = tid & 31;
    int n0 = (blockIdx.x * 8 + warp) * 4;       // 8 warps x 4 nodes
    if (n0 >= NTOT) return;

    float xv[4], av[4];
#pragma unroll
    for (int p = 0; p < 4; p++) {
        xv[p] = x[(size_t)(n0 + p) * DD + lane];
        av[p] = g_agg[(size_t)(n0 + p) * DD + lane];
    }
    float r1[4] = {0.f,0.f,0.f,0.f}, l1[4] = {0.f,0.f,0.f,0.f};
    float r2[4] = {0.f,0.f,0.f,0.f}, l2[4] = {0.f,0.f,0.f,0.f};

#pragma unroll
    for (int k = 0; k < DD; k++) {
        float w0 = sW[0][k * DD + lane];
        float w1 = sW[1][k * DD + lane];
        float w2 = sW[2][k * DD + lane];
        float w3 = sW[3][k * DD + lane];
#pragma unroll
        for (int p = 0; p < 4; p++) {
            float xk = __shfl_sync(FULLMASK, xv[p], k);
            float ak = __shfl_sync(FULLMASK, av[p], k);
            r1[p] = fmaf(xk, w0, r1[p]);  l1[p] = fmaf(ak, w1, l1[p]);
            r2[p] = fmaf(xk, w2, r2[p]);  l2[p] = fmaf(ak, w3, l2[p]);
        }
    }
    float bb1 = b1[lane], bb2 = b2[lane];
    const float SQRT32 = 5.65685415267944336f;
#pragma unroll
    for (int p = 0; p < 4; p++) {
        float o1 = __fadd_rn(__fadd_rn(r1[p], l1[p]), bb1);
        float o2 = __fadd_rn(__fadd_rn(r2[p], l2[p]), bb2);
        float pr = __fmul_rn(o1, o2);
        float s = 0.f;
#pragma unroll
        for (int k = 0; k < DD; k++)            // sequential ascending-d sum
            s = __fadd_rn(s, __shfl_sync(FULLMASK, pr, k));
        if (lane == 0)
            g_score[n0 + p] = __fdiv_rn(s, SQRT32);
    }
}

// ---------------------------------------------------------------------------
// Kernel 7: per-graph top-K (bitonic sort of 2048 packed keys) FUSED with
// layer 3 + skip connection for kept rows.
// key = (~ordered(score) << 32) | index -> ascending == score desc,
// index-asc tiebreak (matches lax.top_k).
// Writes g_newidx for ALL nodes (kept -> row, dropped -> -1).
// Layer-3 FMA chain identical bits to previous k_x5.
// ---------------------------------------------------------------------------
__global__ void __launch_bounds__(1024) k_topk(const float* __restrict__ x,
                                               const float* __restrict__ Wr3,
                                               const float* __restrict__ Wl3,
                                               const float* __restrict__ b3,
                                               float* __restrict__ out) {
    __shared__ unsigned long long key[NPG];
    __shared__ float sW[2][DD * DD];
    int b = blockIdx.x, tid = threadIdx.x;

    for (int i = tid; i < DD * DD; i += 1024) {
        sW[0][i] = Wr3[i]; sW[1][i] = Wl3[i];
    }
    for (int j = tid; j < NPG; j += 1024) {
        float s = g_score[b * NPG + j];
        unsigned u = __float_as_uint(s);
        u = (u & 0x80000000u) ? ~u : (u | 0x80000000u);
        key[j] = ((unsigned long long)(~u) << 32) | (unsigned)j;
    }
    __syncthreads();

    for (int k = 2; k <= NPG; k <<= 1) {
        for (int j = k >> 1; j > 0; j >>= 1) {
            for (int t = tid; t < NPG; t += 1024) {
                int l = t ^ j;
                if (l > t) {
                    bool asc = ((t & k) == 0);
                    unsigned long long a = key[t], c = key[l];
                    if ((a > c) == asc) { key[t] = c; key[l] = a; }
                }
            }
            __syncthreads();
        }
    }

    // Phase 1: relabel map for ALL nodes + scalar outputs for kept ranks.
    {
        int liK = (int)(key[tid] & 0xffffffffu);          // rank tid  (< KKEEP)
        int liD = (int)(key[tid + KKEEP] & 0xffffffffu);  // rank tid+K (dropped)
        int row = b * KKEEP + tid;
        g_newidx[b * NPG + liK] = row;
        g_newidx[b * NPG + liD] = -1;
        out[PERM_OFF + row]   = (float)(b * NPG + liK);
        out[NBATCH_OFF + row] = (float)b;
        out[SC_OFF + row]     = g_score[b * NPG + liK];
    }
    __syncthreads();

    // Phase 2: x5 for kept rows. Warp w handles ranks [w*32, w*32+32).
    int warp = tid >> 5, lane = tid & 31;
    for (int i = 0; i < 32; i++) {
        int rank = warp * 32 + i;
        int node = b * NPG + (int)(key[rank] & 0xffffffffu);
        int row  = b * KKEEP + rank;

        float xv = x[(size_t)node * DD + lane];
        float av = g_agg[(size_t)node * DD + lane];
        float r3 = 0.f, l3 = 0.f;
#pragma unroll
        for (int k = 0; k < DD; k++) {
            float xk = __shfl_sync(FULLMASK, xv, k);
            float ak = __shfl_sync(FULLMASK, av, k);
            r3 = fmaf(xk, sW[0][k * DD + lane], r3);
            l3 = fmaf(ak, sW[1][k * DD + lane], l3);
        }
        float o3 = __fadd_rn(__fadd_rn(r3, l3), b3[lane]);
        float s  = g_score[node];
        out[X5_OFF + (size_t)row * DD + lane] = __fadd_rn(xv, __fmul_rn(s, o3));
    }
}

// ---------------------------------------------------------------------------
// Kernel 8: edge relabel / filter
// ---------------------------------------------------------------------------
__global__ void k_edge(const int* __restrict__ ei, const float* __restrict__ attr,
                       float* __restrict__ out) {
    int e = blockIdx.x * blockDim.x + threadIdx.x;
    if (e >= ETOT) return;
    int ns = g_newidx[ei[e]];
    int nd = g_newidx[ei[ETOT + e]];
    bool v = (ns >= 0) && (nd >= 0);
    out[EI_OFF + e]        = v ? (float)ns : -1.0f;
    out[EI_OFF + ETOT + e] = v ? (float)nd : -1.0f;
    out[EA_OFF + e]        = v ? attr[e] : 0.0f;
}

// ---------------------------------------------------------------------------
// Launch
// ---------------------------------------------------------------------------
extern "C" void kernel_launch(void* const* d_in, const int* in_sizes, int n_in,
                              void* d_out, int out_size) {
    const float* x    = (const float*)d_in[0];
    const int*   ei   = (const int*)d_in[1];
    const float* attr = (const float*)d_in[2];
    // d_in[3] = batch (unused; new_batch derived from graph id)
    const float* Wr1 = (const float*)d_in[4];
    const float* Wl1 = (const float*)d_in[5];
    const float* b1  = (const float*)d_in[6];
    const float* Wr2 = (const float*)d_in[7];
    const float* Wl2 = (const float*)d_in[8];
    const float* b2  = (const float*)d_in[9];
    const float* Wr3 = (const float*)d_in[10];
    const float* Wl3 = (const float*)d_in[11];
    const float* b3  = (const float*)d_in[12];
    float* out = (float*)d_out;

    k_init  <<<(NTOT + 255) / 256, 256>>>();
    k_count <<<(ETOT + 255) / 256, 256>>>(ei);
    k_scan  <<<NB, 1024>>>();
    k_fill  <<<(ETOT + 255) / 256, 256>>>(ei);
    k_gather<<<(NTOT + 7) / 8, 256>>>(x);
    k_trans <<<NTOT / 32, 256>>>(x, Wr1, Wl1, b1, Wr2, Wl2, b2);
    k_topk  <<<NB, 1024>>>(x, Wr3, Wl3, b3, out);
    k_edge  <<<(ETOT + 255) / 256, 256>>>(ei, attr, out);
}